// round 6
// baseline (speedup 1.0000x reference)
#include <cuda_runtime.h>
#include <cuda_bf16.h>
#include <cstdint>

// ---------------- problem dims (fixed by dataset) ----------------
#define T_STEPS 512
#define BATCH   128
#define SDIM    1024
#define ODIM    256
#define JDIM    (SDIM + ODIM)   // 1280

// ---------------- tiling ----------------
#define NPAIR 4              // CTA batch-pairs; each CTA runs 2 independent groups
#define NJ 32                // j tiles
#define GR 16                // batch rows per group
#define JT 40                // j cols per CTA
#define NCTAS (NPAIR * NJ)   // 128 CTAs, one per SM
#define NTHREADS 256
#define NWARPS 8
#define KSLICE 128           // K slice per warp (split-K over 8 warps)
#define CLUSTER 4            // multicast group (4 jtiles of same pair)
#define PAD 8                // bf16 pad per smem row (16B)
#define GSTRIDE (SDIM + PAD) // 1032 halves per smem row
#define ROW_BYTES (SDIM * 2) // 2048 contiguous bytes per G row in gmem
#define EHALF (GR * JT)      // 640 elements per group tile
#define NPROD 26             // jtiles 0..25 produce h columns

// smem layout (bytes): 32-row G tile (A rows 0-15, B rows 16-31) + shared partials
#define SG_BYTES (2 * GR * GSTRIDE * 2)        // 66048
#define SP_BYTES (NWARPS * EHALF * 4)          // 20480 (reused by both groups)
#define SMEM_TOTAL (SG_BYTES + SP_BYTES + 16)  // + two mbarriers

// ---------------- device globals (scratch; no allocation allowed) ----------------
__device__ __align__(16) __nv_bfloat16 g_W[(size_t)JDIM * SDIM];      // concat(w_r, w_o), bf16
__device__ __align__(16) __nv_bfloat16 g_G[2][(size_t)BATCH * SDIM];  // tanh(h), double-buffered
__device__ unsigned g_slotsA[NPAIR * 32];  // group A (rows 0-15 of pair) arrivals
__device__ unsigned g_slotsB[NPAIR * 32];  // group B (rows 16-31 of pair) arrivals

// ---------------- helpers ----------------
__device__ __forceinline__ unsigned ld_acq(const unsigned* p) {
    unsigned v;
    asm volatile("ld.acquire.gpu.global.u32 %0, [%1];" : "=r"(v) : "l"(p));
    return v;
}
__device__ __forceinline__ void st_rel(unsigned* p, unsigned v) {
    asm volatile("st.release.gpu.global.u32 [%0], %1;" :: "l"(p), "r"(v) : "memory");
}
__device__ __forceinline__ float tanh_fast(float v) {
    float r;
    asm("tanh.approx.f32 %0, %1;" : "=f"(r) : "f"(v));
    return r;
}
__device__ __forceinline__ void mma16816(float c[4], const unsigned a[4],
                                         unsigned b0, unsigned b1) {
    asm volatile(
        "mma.sync.aligned.m16n8k16.row.col.f32.bf16.bf16.f32 "
        "{%0,%1,%2,%3}, {%4,%5,%6,%7}, {%8,%9}, {%0,%1,%2,%3};\n"
        : "+f"(c[0]), "+f"(c[1]), "+f"(c[2]), "+f"(c[3])
        : "r"(a[0]), "r"(a[1]), "r"(a[2]), "r"(a[3]), "r"(b0), "r"(b1));
}
__device__ __forceinline__ void ldsm_x4(unsigned a[4], uint32_t addr) {
    asm volatile("ldmatrix.sync.aligned.m8n8.x4.shared.b16 {%0,%1,%2,%3}, [%4];"
                 : "=r"(a[0]), "=r"(a[1]), "=r"(a[2]), "=r"(a[3]) : "r"(addr));
}
__device__ __forceinline__ void mbar_wait(uint32_t mbar, unsigned parity) {
    asm volatile(
        "{\n\t"
        ".reg .pred P;\n\t"
        "WL_%=:\n\t"
        "mbarrier.try_wait.parity.acquire.cta.shared::cta.b64 P, [%0], %1, 0x989680;\n\t"
        "@P bra.uni WD_%=;\n\t"
        "bra.uni WL_%=;\n\t"
        "WD_%=:\n\t"
        "}" :: "r"(mbar), "r"(parity) : "memory");
}

// ---------------- init: bf16 weights + G0 = tanh(h_init), reset barrier slots ----------------
__global__ void trnn_init(const float* __restrict__ w_r, const float* __restrict__ w_o,
                          const float* __restrict__ h_init) {
    size_t stride = (size_t)gridDim.x * blockDim.x;
    size_t i0 = (size_t)blockIdx.x * blockDim.x + threadIdx.x;
    const size_t WR_N = (size_t)SDIM * SDIM;
    const size_t W_N  = (size_t)JDIM * SDIM;
    for (size_t i = i0; i < W_N; i += stride) {
        float v = (i < WR_N) ? w_r[i] : w_o[i - WR_N];
        g_W[i] = __float2bfloat16(v);
    }
    for (size_t i = i0; i < (size_t)BATCH * SDIM; i += stride) {
        g_G[0][i] = __float2bfloat16(tanhf(h_init[i]));
    }
    if (i0 < NPAIR * 32) { g_slotsA[i0] = 0u; g_slotsB[i0] = 0u; }
}

// ---------------- persistent kernel: two independent phase-shifted recurrences/CTA ----------------
__global__ void __launch_bounds__(NTHREADS, 1) __cluster_dims__(CLUSTER, 1, 1)
trnn_persistent(const float* __restrict__ x, const float* __restrict__ h_init,
                const float* __restrict__ b_r, const float* __restrict__ b_o,
                float* __restrict__ out) {
    extern __shared__ char smem[];
    __nv_bfloat16* sG = (__nv_bfloat16*)smem;
    float* sP = (float*)(smem + SG_BYTES);
    uint32_t mbarA = (uint32_t)__cvta_generic_to_shared(smem + SG_BYTES + SP_BYTES);
    uint32_t mbarB = mbarA + 8;

    const int tid  = threadIdx.x;
    const int warp = tid >> 5;
    const int lane = tid & 31;
    const int grp  = lane >> 2;   // 0..7
    const int tig  = lane & 3;    // 0..3
    const int pair  = blockIdx.x >> 5;  // 0..3
    const int jtile = blockIdx.x & 31;
    const int rank  = blockIdx.x & (CLUSTER - 1);
    const int b0 = pair * 32;           // group A rows b0..b0+15, B rows b0+16..b0+31
    const int j0 = jtile * JT;
    const int kw = warp * KSLICE;
    const bool producer = (jtile < NPROD);

    unsigned* slotsA = &g_slotsA[pair * 32];
    unsigned* slotsB = &g_slotsB[pair * 32];
    unsigned* relA = slotsA + jtile;
    unsigned* relB = slotsB + jtile;

    if (tid == 0) {
        asm volatile("mbarrier.init.shared.b64 [%0], 1;" :: "r"(mbarA) : "memory");
        asm volatile("mbarrier.init.shared.b64 [%0], 1;" :: "r"(mbarB) : "memory");
    }
    __syncthreads();
    asm volatile("barrier.cluster.arrive.aligned;" ::: "memory");
    asm volatile("barrier.cluster.wait.aligned;"   ::: "memory");

    // --- per-thread persistent epilogue state; e = d*256 + tid (< 640 valid) ---
    int ej[3]; int erow[3]; float bv[3]; float hr[2][3];
    #pragma unroll
    for (int d = 0; d < 3; ++d) {
        int e = d * NTHREADS + tid;
        if (e < EHALF) {
            int r = e / JT;
            int j = j0 + (e % JT);
            ej[d] = j; erow[d] = r;
            if (j < SDIM) {
                bv[d] = b_r[j];
                hr[0][d] = h_init[(size_t)(b0 + r) * SDIM + j];
                hr[1][d] = h_init[(size_t)(b0 + 16 + r) * SDIM + j];
            } else {
                bv[d] = b_o[j - SDIM];
                hr[0][d] = 0.f; hr[1][d] = 0.f;
            }
        } else { ej[d] = -1; erow[d] = 0; bv[d] = 0.f; hr[0][d] = 0.f; hr[1][d] = 0.f; }
    }

    // --- W fragments: persistent in registers across all steps (80 regs/thread) ---
    unsigned Breg[8][5][2];
    #pragma unroll
    for (int ks = 0; ks < 8; ++ks) {
        #pragma unroll
        for (int ni = 0; ni < 5; ++ni) {
            int jr = ni * 8 + grp;
            const unsigned* wp = (const unsigned*)(g_W + (size_t)(j0 + jr) * SDIM + kw + ks * 16);
            Breg[ks][ni][0] = wp[tig];
            Breg[ks][ni][1] = wp[4 + tig];
        }
    }
    __syncthreads();

    // --- ldmatrix per-lane base addresses (group A rows 0-15, group B rows 16-31) ---
    const uint32_t sGb = (uint32_t)__cvta_generic_to_shared(sG);
    const int rl = lane & 15;
    const int khalf = (lane & 16) ? 8 : 0;
    const uint32_t aBaseA = sGb + (uint32_t)((rl * GSTRIDE + kw + khalf) * 2);
    const uint32_t aBaseB = aBaseA + (uint32_t)(16 * GSTRIDE * 2);

    for (int it = 0; it <= T_STEPS; ++it) {
        const unsigned parity = (unsigned)(it & 1);
        const __nv_bfloat16* Gc = g_G[it & 1];
        __nv_bfloat16* Gn = g_G[(it + 1) & 1];

        // --- expect_tx for both group tiles (prior phases complete) ---
        if (tid == 0) {
            asm volatile("mbarrier.arrive.expect_tx.shared.b64 _, [%0], %1;"
                         :: "r"(mbarA), "r"(GR * ROW_BYTES) : "memory");
            asm volatile("mbarrier.arrive.expect_tx.shared.b64 _, [%0], %1;"
                         :: "r"(mbarB), "r"(GR * ROW_BYTES) : "memory");
        }

        // --- x prefetch for both groups (off critical path) ---
        float xr[2][3];
        if (it >= 1) {
            #pragma unroll
            for (int g = 0; g < 2; ++g)
                #pragma unroll
                for (int d = 0; d < 3; ++d)
                    if (ej[d] >= SDIM) {
                        size_t oi = ((size_t)(it - 1) * BATCH + (b0 + g * 16 + erow[d])) * ODIM
                                    + (ej[d] - SDIM);
                        xr[g][d] = __ldcs(x + oi);
                    }
        }

        // --- poll group A (released one whole B-phase ago -> hop hidden) ---
        if (it > 0 && warp == 0) {
            const unsigned phase = (unsigned)it;
            for (;;) {
                unsigned v = ld_acq(&slotsA[lane]);
                if (__all_sync(0xffffffffu, v >= phase)) break;
            }
        }
        // --- TMA group A: 4 rows/CTA multicast to cluster ---
        if (tid == 0) {
            asm volatile("fence.proxy.async;" ::: "memory");
            #pragma unroll
            for (int rr = 0; rr < 4; ++rr) {
                int lr = rank * 4 + rr;
                const void* src = (const void*)(Gc + (size_t)(b0 + lr) * SDIM);
                uint32_t dst = (uint32_t)__cvta_generic_to_shared(sG + lr * GSTRIDE);
                asm volatile(
                    "cp.async.bulk.shared::cluster.global.mbarrier::complete_tx::bytes"
                    ".multicast::cluster [%0], [%1], %2, [%3], %4;"
                    :: "r"(dst), "l"(src), "r"(ROW_BYTES), "r"(mbarA),
                       "h"((unsigned short)((1u << CLUSTER) - 1u))
                    : "memory");
            }
        }

        // ================= group A compute =================
        float yvA[3];
        {
            mbar_wait(mbarA, parity);
            float acc[5][4];
            #pragma unroll
            for (int ni = 0; ni < 5; ++ni)
                #pragma unroll
                for (int q = 0; q < 4; ++q) acc[ni][q] = 0.f;
            #pragma unroll
            for (int ks = 0; ks < 8; ++ks) {
                unsigned a[4];
                ldsm_x4(a, aBaseA + ks * 32);
                #pragma unroll
                for (int ni = 0; ni < 5; ++ni)
                    mma16816(acc[ni], a, Breg[ks][ni][0], Breg[ks][ni][1]);
            }

            // --- poll + TMA group B (released one A-phase ago -> hop mostly hidden) ---
            if (it > 0 && warp == 0) {
                const unsigned phase = (unsigned)it;
                for (;;) {
                    unsigned v = ld_acq(&slotsB[lane]);
                    if (__all_sync(0xffffffffu, v >= phase)) break;
                }
            }
            if (tid == 0) {
                asm volatile("fence.proxy.async;" ::: "memory");
                #pragma unroll
                for (int rr = 0; rr < 4; ++rr) {
                    int lr = 16 + rank * 4 + rr;
                    const void* src = (const void*)(Gc + (size_t)(b0 + lr) * SDIM);
                    uint32_t dst = (uint32_t)__cvta_generic_to_shared(sG + lr * GSTRIDE);
                    asm volatile(
                        "cp.async.bulk.shared::cluster.global.mbarrier::complete_tx::bytes"
                        ".multicast::cluster [%0], [%1], %2, [%3], %4;"
                        :: "r"(dst), "l"(src), "r"(ROW_BYTES), "r"(mbarB),
                           "h"((unsigned short)((1u << CLUSTER) - 1u))
                        : "memory");
                }
            }

            // STS A partials
            float* p = sP + warp * EHALF;
            #pragma unroll
            for (int ni = 0; ni < 5; ++ni) {
                int cc = ni * 8 + tig * 2;
                *(float2*)&p[grp * JT + cc]       = make_float2(acc[ni][0], acc[ni][1]);
                *(float2*)&p[(grp + 8) * JT + cc] = make_float2(acc[ni][2], acc[ni][3]);
            }
            __syncthreads();   // sync1: A partials in, all sG-A reads done
            if (!producer && tid == 0) st_rel(relA, (unsigned)(it + 1));

            #pragma unroll
            for (int d = 0; d < 3; ++d) {
                int e = d * NTHREADS + tid;
                if (e < EHALF) {
                    float y = sP[e];
                    #pragma unroll
                    for (int w = 1; w < NWARPS; ++w) y += sP[w * EHALF + e];
                    yvA[d] = y;
                    if (ej[d] < SDIM) {
                        float hv = 0.75f * hr[0][d] + 0.25f * (y + bv[d]);
                        hr[0][d] = hv;
                        Gn[(size_t)(b0 + erow[d]) * SDIM + ej[d]] =
                            __float2bfloat16(tanh_fast(hv));
                    }
                }
            }
            __syncthreads();   // sync2: A G-stores done, sP reads done
            if (producer && tid == 0) st_rel(relA, (unsigned)(it + 1));
        }

        // ================= group B compute =================
        float yvB[3];
        {
            mbar_wait(mbarB, parity);
            float acc[5][4];
            #pragma unroll
            for (int ni = 0; ni < 5; ++ni)
                #pragma unroll
                for (int q = 0; q < 4; ++q) acc[ni][q] = 0.f;
            #pragma unroll
            for (int ks = 0; ks < 8; ++ks) {
                unsigned a[4];
                ldsm_x4(a, aBaseB + ks * 32);
                #pragma unroll
                for (int ni = 0; ni < 5; ++ni)
                    mma16816(acc[ni], a, Breg[ks][ni][0], Breg[ks][ni][1]);
            }
            float* p = sP + warp * EHALF;
            #pragma unroll
            for (int ni = 0; ni < 5; ++ni) {
                int cc = ni * 8 + tig * 2;
                *(float2*)&p[grp * JT + cc]       = make_float2(acc[ni][0], acc[ni][1]);
                *(float2*)&p[(grp + 8) * JT + cc] = make_float2(acc[ni][2], acc[ni][3]);
            }
            __syncthreads();   // sync3
            if (!producer && tid == 0) st_rel(relB, (unsigned)(it + 1));

            #pragma unroll
            for (int d = 0; d < 3; ++d) {
                int e = d * NTHREADS + tid;
                if (e < EHALF) {
                    float y = sP[e];
                    #pragma unroll
                    for (int w = 1; w < NWARPS; ++w) y += sP[w * EHALF + e];
                    yvB[d] = y;
                    if (ej[d] < SDIM) {
                        float hv = 0.75f * hr[1][d] + 0.25f * (y + bv[d]);
                        hr[1][d] = hv;
                        Gn[(size_t)(b0 + 16 + erow[d]) * SDIM + ej[d]] =
                            __float2bfloat16(tanh_fast(hv));
                    }
                }
            }
            __syncthreads();   // sync4
            if (producer && tid == 0) st_rel(relB, (unsigned)(it + 1));
        }

        // --- outputs (off the critical path) ---
        if (it >= 1) {
            #pragma unroll
            for (int d = 0; d < 3; ++d) {
                if (ej[d] >= SDIM) {
                    int o = ej[d] - SDIM;
                    size_t row = (size_t)(it - 1) * BATCH + b0 + erow[d];
                    out[row * ODIM + o]              = yvA[d] + bv[d] - xr[0][d];
                    out[(row + 16) * ODIM + o]       = yvB[d] + bv[d] - xr[1][d];
                }
            }
        }
    }

    // no CTA may exit while peers' multicast writes into its smem are possible
    asm volatile("barrier.cluster.arrive.aligned;" ::: "memory");
    asm volatile("barrier.cluster.wait.aligned;"   ::: "memory");
}

// ---------------- launch ----------------
extern "C" void kernel_launch(void* const* d_in, const int* in_sizes, int n_in,
                              void* d_out, int out_size) {
    const float *x = nullptr, *h = nullptr, *wr = nullptr, *br = nullptr,
                *wo = nullptr, *bo = nullptr;
    for (int i = 0; i < n_in; ++i) {
        switch (in_sizes[i]) {
            case 512 * 128 * 256: x  = (const float*)d_in[i]; break;  // 16777216
            case 128 * 1024:      h  = (const float*)d_in[i]; break;  // 131072
            case 1024 * 1024:     wr = (const float*)d_in[i]; break;  // 1048576
            case 1024:            br = (const float*)d_in[i]; break;
            case 256 * 1024:      wo = (const float*)d_in[i]; break;  // 262144
            case 256:             bo = (const float*)d_in[i]; break;
            default: break;
        }
    }
    cudaFuncSetAttribute(trnn_persistent,
                         cudaFuncAttributeMaxDynamicSharedMemorySize, SMEM_TOTAL);
    trnn_init<<<512, 256>>>(wr, wo, h);
    trnn_persistent<<<NCTAS, NTHREADS, SMEM_TOTAL>>>(x, h, br, bo, (float*)d_out);
}

// round 7
// speedup vs baseline: 1.1744x; 1.1744x over previous
#include <cuda_runtime.h>
#include <cuda_bf16.h>
#include <cstdint>

// ---------------- problem dims (fixed by dataset) ----------------
#define T_STEPS 512
#define BATCH   128
#define SDIM    1024
#define ODIM    256
#define JDIM    (SDIM + ODIM)   // 1280

// ---------------- tiling ----------------
#define NB 4                 // batch tiles (independent recurrence groups)
#define NJ 32                // j tiles
#define BT 32                // batch rows per CTA
#define JT 40                // j cols per CTA
#define NCTAS (NB * NJ)      // 128 CTAs, one per SM
#define NTHREADS 256
#define NWARPS 8
#define KSLICE 128           // K slice per warp (split-K over 8 warps)
#define CLUSTER 4
#define ROWS_PER_CTA (BT / CLUSTER)   // 8 rows loaded+multicast per CTA
#define PAD 8
#define GSTRIDE (SDIM + PAD) // 1032 halves per smem row
#define ROW_BYTES (SDIM * 2) // 2048 B per G row in gmem
// K-split of the G broadcast: lo = cols [0,640) (jtiles 0-15), hi = [640,1024) (jtiles 16-25)
#define KSPLIT   640
#define LO_BYTES (KSPLIT * 2)             // 1280
#define HI_BYTES ((SDIM - KSPLIT) * 2)    // 768
#define NPROD_LO 16
#define NPROD_HI 26

// smem layout (bytes)
#define SG_BYTES (BT * GSTRIDE * 2)            // 66048
#define SP_BYTES (NWARPS * BT * JT * 4)        // 40960
#define SMEM_TOTAL (SG_BYTES + SP_BYTES + 16)  // + two mbarriers

// ---------------- device globals ----------------
__device__ __align__(16) __nv_bfloat16 g_W[(size_t)JDIM * SDIM];
__device__ __align__(16) __nv_bfloat16 g_G[2][(size_t)BATCH * SDIM];
__device__ unsigned g_relLo[NB * 32];   // per-CTA: G cols[0,640) stored (producers) / lo reads done
__device__ unsigned g_relHi[NB * 32];   // per-CTA: G cols[640,1024) stored / hi reads done

// ---------------- helpers ----------------
__device__ __forceinline__ unsigned ld_acq(const unsigned* p) {
    unsigned v;
    asm volatile("ld.acquire.gpu.global.u32 %0, [%1];" : "=r"(v) : "l"(p));
    return v;
}
__device__ __forceinline__ void st_rel(unsigned* p, unsigned v) {
    asm volatile("st.release.gpu.global.u32 [%0], %1;" :: "l"(p), "r"(v) : "memory");
}
__device__ __forceinline__ float tanh_fast(float v) {
    float r;
    asm("tanh.approx.f32 %0, %1;" : "=f"(r) : "f"(v));
    return r;
}
__device__ __forceinline__ void mma16816(float c[4], const unsigned a[4],
                                         unsigned b0, unsigned b1) {
    asm volatile(
        "mma.sync.aligned.m16n8k16.row.col.f32.bf16.bf16.f32 "
        "{%0,%1,%2,%3}, {%4,%5,%6,%7}, {%8,%9}, {%0,%1,%2,%3};\n"
        : "+f"(c[0]), "+f"(c[1]), "+f"(c[2]), "+f"(c[3])
        : "r"(a[0]), "r"(a[1]), "r"(a[2]), "r"(a[3]), "r"(b0), "r"(b1));
}
__device__ __forceinline__ void ldsm_x4(unsigned a[4], uint32_t addr) {
    asm volatile("ldmatrix.sync.aligned.m8n8.x4.shared.b16 {%0,%1,%2,%3}, [%4];"
                 : "=r"(a[0]), "=r"(a[1]), "=r"(a[2]), "=r"(a[3]) : "r"(addr));
}
__device__ __forceinline__ void mbar_wait(uint32_t mbar, unsigned parity) {
    asm volatile(
        "{\n\t"
        ".reg .pred P;\n\t"
        "WL_%=:\n\t"
        "mbarrier.try_wait.parity.acquire.cta.shared::cta.b64 P, [%0], %1, 0x989680;\n\t"
        "@P bra.uni WD_%=;\n\t"
        "bra.uni WL_%=;\n\t"
        "WD_%=:\n\t"
        "}" :: "r"(mbar), "r"(parity) : "memory");
}
// whole-warp poll of 32 slots, but only lanes in `mask` must reach `phase`
__device__ __forceinline__ void poll_mask(unsigned* slots, unsigned mask,
                                          unsigned phase, int lane) {
    const bool active = (mask >> lane) & 1u;
    for (;;) {
        unsigned v = active ? ld_acq(&slots[lane]) : phase;
        if (__all_sync(0xffffffffu, v >= phase)) break;
    }
}

// ---------------- init ----------------
__global__ void trnn_init(const float* __restrict__ w_r, const float* __restrict__ w_o,
                          const float* __restrict__ h_init) {
    size_t stride = (size_t)gridDim.x * blockDim.x;
    size_t i0 = (size_t)blockIdx.x * blockDim.x + threadIdx.x;
    const size_t WR_N = (size_t)SDIM * SDIM;
    const size_t W_N  = (size_t)JDIM * SDIM;
    for (size_t i = i0; i < W_N; i += stride) {
        float v = (i < WR_N) ? w_r[i] : w_o[i - WR_N];
        g_W[i] = __float2bfloat16(v);
    }
    for (size_t i = i0; i < (size_t)BATCH * SDIM; i += stride) {
        g_G[0][i] = __float2bfloat16(tanhf(h_init[i]));
    }
    if (i0 < NB * 32) { g_relLo[i0] = 0u; g_relHi[i0] = 0u; }
}

// ---------------- persistent kernel: K-split broadcast pipeline ----------------
__global__ void __launch_bounds__(NTHREADS, 1) __cluster_dims__(CLUSTER, 1, 1)
trnn_persistent(const float* __restrict__ x, const float* __restrict__ h_init,
                const float* __restrict__ b_r, const float* __restrict__ b_o,
                float* __restrict__ out) {
    extern __shared__ char smem[];
    __nv_bfloat16* sG = (__nv_bfloat16*)smem;
    float* sP = (float*)(smem + SG_BYTES);
    uint32_t mbarLo = (uint32_t)__cvta_generic_to_shared(smem + SG_BYTES + SP_BYTES);
    uint32_t mbarHi = mbarLo + 8;

    const int tid  = threadIdx.x;
    const int warp = tid >> 5;
    const int lane = tid & 31;
    const int grp  = lane >> 2;
    const int tig  = lane & 3;
    const int btile = blockIdx.x >> 5;
    const int jtile = blockIdx.x & 31;
    const int rank  = blockIdx.x & (CLUSTER - 1);
    const int b0 = btile * BT;
    const int j0 = jtile * JT;
    const int kw = warp * KSLICE;
    const bool loWarp = (kw < KSPLIT);            // warps 0-4 read cols [0,640)
    const bool prodLo = (jtile < NPROD_LO);       // produces G cols in [0,640)
    const bool prodHi = (jtile >= NPROD_LO && jtile < NPROD_HI);

    unsigned* slotsLo = &g_relLo[btile * 32];
    unsigned* slotsHi = &g_relHi[btile * 32];
    unsigned* relLo = slotsLo + jtile;
    unsigned* relHi = slotsHi + jtile;

    const unsigned peerMask = 0xFu << (jtile & ~3);
    const unsigned M_LO = 0x0000FFFFu | peerMask;
    const unsigned M_HI = 0x03FF0000u | peerMask;

    if (tid == 0) {
        asm volatile("mbarrier.init.shared.b64 [%0], 1;" :: "r"(mbarLo) : "memory");
        asm volatile("mbarrier.init.shared.b64 [%0], 1;" :: "r"(mbarHi) : "memory");
    }
    __syncthreads();
    asm volatile("barrier.cluster.arrive.aligned;" ::: "memory");
    asm volatile("barrier.cluster.wait.aligned;"   ::: "memory");

    // --- per-thread persistent epilogue state (flat: e = d*256 + tid over 1280) ---
    int ej[5]; int ebl[5]; float hr[5]; float bv[5];
    #pragma unroll
    for (int d = 0; d < 5; ++d) {
        int e = d * NTHREADS + tid;
        int bl = e / JT, jl = e - bl * JT;
        int j = j0 + jl;
        ej[d] = j; ebl[d] = bl;
        if (j < SDIM) {
            hr[d] = h_init[(size_t)(b0 + bl) * SDIM + j];
            bv[d] = b_r[j];
        } else {
            hr[d] = 0.f;
            bv[d] = b_o[j - SDIM];
        }
    }

    // --- W fragments persistent in registers (80 regs/thread) ---
    unsigned Breg[8][5][2];
    #pragma unroll
    for (int ks = 0; ks < 8; ++ks) {
        #pragma unroll
        for (int ni = 0; ni < 5; ++ni) {
            int jr = ni * 8 + grp;
            const unsigned* wp = (const unsigned*)(g_W + (size_t)(j0 + jr) * SDIM + kw + ks * 16);
            Breg[ks][ni][0] = wp[tig];
            Breg[ks][ni][1] = wp[4 + tig];
        }
    }
    __syncthreads();

    // --- ldmatrix per-lane base addresses (rows 0-15 / 16-31 within warp kslice) ---
    const uint32_t sGb = (uint32_t)__cvta_generic_to_shared(sG);
    const int rl = lane & 15;
    const int khalf = (lane & 16) ? 8 : 0;
    const uint32_t aBase0 = sGb + (uint32_t)((rl * GSTRIDE + kw + khalf) * 2);
    const uint32_t aBase1 = aBase0 + (uint32_t)(16 * GSTRIDE * 2);

    for (int it = 0; it <= T_STEPS; ++it) {
        const unsigned parity = (unsigned)(it & 1);
        const unsigned phase = (unsigned)it;
        const __nv_bfloat16* Gc = g_G[it & 1];
        __nv_bfloat16* Gn = g_G[(it + 1) & 1];

        // --- x prefetch (off critical path) ---
        float xr[5];
        if (it >= 1) {
            #pragma unroll
            for (int d = 0; d < 5; ++d)
                if (ej[d] >= SDIM) {
                    size_t oi = ((size_t)(it - 1) * BATCH + (b0 + ebl[d])) * ODIM + (ej[d] - SDIM);
                    xr[d] = __ldcs(x + oi);
                }
        }

        // --- warp 0: poll lo producers + peers, then tid0 issues lo TMA segments ---
        if (warp == 0) {
            if (it > 0) poll_mask(slotsLo, M_LO, phase, lane);
            if (lane == 0) {
                asm volatile("mbarrier.arrive.expect_tx.shared.b64 _, [%0], %1;"
                             :: "r"(mbarLo), "r"(BT * LO_BYTES) : "memory");
                asm volatile("fence.proxy.async;" ::: "memory");
                #pragma unroll
                for (int rr = 0; rr < ROWS_PER_CTA; ++rr) {
                    int r = rank * ROWS_PER_CTA + rr;
                    const void* src = (const void*)(Gc + (size_t)(b0 + r) * SDIM);
                    uint32_t dst = (uint32_t)__cvta_generic_to_shared(sG + r * GSTRIDE);
                    asm volatile(
                        "cp.async.bulk.shared::cluster.global.mbarrier::complete_tx::bytes"
                        ".multicast::cluster [%0], [%1], %2, [%3], %4;"
                        :: "r"(dst), "l"(src), "r"(LO_BYTES), "r"(mbarLo),
                           "h"((unsigned short)0xF) : "memory");
                }
            }
        }
        // --- warp 7: poll hi producers + peers, then tid 224 issues hi TMA segments ---
        if (warp == 7) {
            if (it > 0) poll_mask(slotsHi, M_HI, phase, lane);
            if (lane == 0) {
                asm volatile("mbarrier.arrive.expect_tx.shared.b64 _, [%0], %1;"
                             :: "r"(mbarHi), "r"(BT * HI_BYTES) : "memory");
                asm volatile("fence.proxy.async;" ::: "memory");
                #pragma unroll
                for (int rr = 0; rr < ROWS_PER_CTA; ++rr) {
                    int r = rank * ROWS_PER_CTA + rr;
                    const void* src = (const void*)(Gc + (size_t)(b0 + r) * SDIM + KSPLIT);
                    uint32_t dst = (uint32_t)__cvta_generic_to_shared(sG + r * GSTRIDE + KSPLIT);
                    asm volatile(
                        "cp.async.bulk.shared::cluster.global.mbarrier::complete_tx::bytes"
                        ".multicast::cluster [%0], [%1], %2, [%3], %4;"
                        :: "r"(dst), "l"(src), "r"(HI_BYTES), "r"(mbarHi),
                           "h"((unsigned short)0xF) : "memory");
                }
            }
        }

        // --- wait only for the half this warp reads, then mma ---
        mbar_wait(loWarp ? mbarLo : mbarHi, parity);

        float acc[2][5][4];
        #pragma unroll
        for (int mi = 0; mi < 2; ++mi)
            #pragma unroll
            for (int ni = 0; ni < 5; ++ni)
                #pragma unroll
                for (int q = 0; q < 4; ++q) acc[mi][ni][q] = 0.f;

        #pragma unroll
        for (int ks = 0; ks < 8; ++ks) {
            unsigned a0[4], a1[4];
            ldsm_x4(a0, aBase0 + ks * 32);
            ldsm_x4(a1, aBase1 + ks * 32);
            #pragma unroll
            for (int ni = 0; ni < 5; ++ni) {
                mma16816(acc[0][ni], a0, Breg[ks][ni][0], Breg[ks][ni][1]);
                mma16816(acc[1][ni], a1, Breg[ks][ni][0], Breg[ks][ni][1]);
            }
        }

        // --- per-warp partials ---
        {
            float* p = sP + warp * (BT * JT);
            #pragma unroll
            for (int mi = 0; mi < 2; ++mi)
                #pragma unroll
                for (int ni = 0; ni < 5; ++ni) {
                    int r = mi * 16 + grp, cc = ni * 8 + tig * 2;
                    *(float2*)&p[r * JT + cc]       = make_float2(acc[mi][ni][0], acc[mi][ni][1]);
                    *(float2*)&p[(r + 8) * JT + cc] = make_float2(acc[mi][ni][2], acc[mi][ni][3]);
                }
        }
        __syncthreads();   // sync1: all partials in, all sG reads done

        // --- early releases: halves this CTA does NOT produce (reads-done signal) ---
        if (tid == 0) {
            if (!prodLo) st_rel(relLo, phase + 1u);
            if (!prodHi) st_rel(relHi, phase + 1u);
        }

        // --- split-K reduce + h update + tanh + G store ---
        float yv[5];
        #pragma unroll
        for (int d = 0; d < 5; ++d) {
            int e = d * NTHREADS + tid;
            float y = sP[e];
            #pragma unroll
            for (int w = 1; w < NWARPS; ++w) y += sP[w * (BT * JT) + e];
            yv[d] = y;
            if (ej[d] < SDIM) {
                float hv = 0.75f * hr[d] + 0.25f * (y + bv[d]);
                hr[d] = hv;
                Gn[(size_t)(b0 + ebl[d]) * SDIM + ej[d]] = __float2bfloat16(tanh_fast(hv));
            }
        }
        __syncthreads();   // sync2: all G stores issued

        // --- producer releases (st.release orders the G stores) ---
        if (tid == 0) {
            if (prodLo) st_rel(relLo, phase + 1u);
            if (prodHi) st_rel(relHi, phase + 1u);
        }

        // --- outputs (off critical path) ---
        if (it >= 1) {
            #pragma unroll
            for (int d = 0; d < 5; ++d)
                if (ej[d] >= SDIM) {
                    size_t oi = ((size_t)(it - 1) * BATCH + (b0 + ebl[d])) * ODIM + (ej[d] - SDIM);
                    out[oi] = yv[d] + bv[d] - xr[d];
                }
        }
    }

    asm volatile("barrier.cluster.arrive.aligned;" ::: "memory");
    asm volatile("barrier.cluster.wait.aligned;"   ::: "memory");
}

// ---------------- launch ----------------
extern "C" void kernel_launch(void* const* d_in, const int* in_sizes, int n_in,
                              void* d_out, int out_size) {
    const float *x = nullptr, *h = nullptr, *wr = nullptr, *br = nullptr,
                *wo = nullptr, *bo = nullptr;
    for (int i = 0; i < n_in; ++i) {
        switch (in_sizes[i]) {
            case 512 * 128 * 256: x  = (const float*)d_in[i]; break;
            case 128 * 1024:      h  = (const float*)d_in[i]; break;
            case 1024 * 1024:     wr = (const float*)d_in[i]; break;
            case 1024:            br = (const float*)d_in[i]; break;
            case 256 * 1024:      wo = (const float*)d_in[i]; break;
            case 256:             bo = (const float*)d_in[i]; break;
            default: break;
        }
    }
    cudaFuncSetAttribute(trnn_persistent,
                         cudaFuncAttributeMaxDynamicSharedMemorySize, SMEM_TOTAL);
    trnn_init<<<512, 256>>>(wr, wo, h);
    trnn_persistent<<<NCTAS, NTHREADS, SMEM_TOTAL>>>(x, h, br, bo, (float*)d_out);
}